// round 12
// baseline (speedup 1.0000x reference)
#include <cuda_runtime.h>
#include <cuda_bf16.h>
#include <float.h>
#include <math.h>
#include <stdint.h>

#define BSZ 4
#define ND 2048
#define NC 8192
#define DM 11
#define DMODEL 256
#define TOPK 32
#define NCAND 64
#define NCMAX 128

// ---------------- scratch (no allocations allowed) ----------------
__device__ float g_xmicro[BSZ * ND * DMODEL];
__device__ float g_Q[BSZ * ND * DMODEL];
__device__ float g_Kf[BSZ * NC * DMODEL];
__device__ float g_Vf[BSZ * NC * DMODEL];
__device__ uint16_t g_keys16[(size_t)BSZ * ND * NC];     // 16-bit radix keys
__device__ __nv_bfloat16 g_Qb[(size_t)BSZ * ND * DMODEL];
__device__ __nv_bfloat16 g_Kb[(size_t)BSZ * NC * DMODEL];
__device__ float g_attn[BSZ * ND * TOPK];
__device__ int   g_idx[BSZ * ND * TOPK];

// ---------------- packed f32x2 helpers ---------------------------------------
__device__ __forceinline__ uint64_t pack2(float lo, float hi) {
    uint64_t d;
    asm("mov.b64 %0, {%1, %2};" : "=l"(d) : "f"(lo), "f"(hi));
    return d;
}
__device__ __forceinline__ void unpack2(uint64_t v, float& lo, float& hi) {
    asm("mov.b64 {%0, %1}, %2;" : "=f"(lo), "=f"(hi) : "l"(v));
}
__device__ __forceinline__ uint64_t ffma2(uint64_t a, uint64_t b, uint64_t c) {
    uint64_t d;
    asm("fma.rn.f32x2 %0, %1, %2, %3;" : "=l"(d) : "l"(a), "l"(b), "l"(c));
    return d;
}

// ---------------- mma.sync / cp.async helpers --------------------------------
__device__ __forceinline__ uint32_t smem_u32(const void* p) {
    uint32_t a;
    asm("{ .reg .u64 t; cvta.to.shared.u64 t, %1; cvt.u32.u64 %0, t; }"
        : "=r"(a) : "l"(p));
    return a;
}
__device__ __forceinline__ void cp16(uint32_t dst, const void* src) {
    asm volatile("cp.async.ca.shared.global [%0], [%1], 16;"
                 :: "r"(dst), "l"(src));
}
__device__ __forceinline__ void cp_commit() {
    asm volatile("cp.async.commit_group;");
}
__device__ __forceinline__ void cp_wait1() {
    asm volatile("cp.async.wait_group 1;");
}
__device__ __forceinline__ void cp_wait0() {
    asm volatile("cp.async.wait_group 0;");
}
__device__ __forceinline__ void ldsm4(uint32_t& r0, uint32_t& r1, uint32_t& r2,
                                      uint32_t& r3, uint32_t addr) {
    asm volatile("ldmatrix.sync.aligned.m8n8.x4.shared.b16 {%0,%1,%2,%3}, [%4];"
                 : "=r"(r0), "=r"(r1), "=r"(r2), "=r"(r3) : "r"(addr));
}
__device__ __forceinline__ void mma16816(float& d0, float& d1, float& d2,
                                         float& d3, uint32_t a0, uint32_t a1,
                                         uint32_t a2, uint32_t a3, uint32_t b0,
                                         uint32_t b1) {
    asm volatile(
        "mma.sync.aligned.m16n8k16.row.col.f32.bf16.bf16.f32 "
        "{%0,%1,%2,%3}, {%4,%5,%6,%7}, {%8,%9}, {%0,%1,%2,%3};"
        : "+f"(d0), "+f"(d1), "+f"(d2), "+f"(d3)
        : "r"(a0), "r"(a1), "r"(a2), "r"(a3), "r"(b0), "r"(b1));
}
__device__ __forceinline__ uint32_t fkey(float v) {
    uint32_t u = __float_as_uint(v);
    return (u & 0x80000000u) ? ~u : (u | 0x80000000u);
}

// ---------------- kernel 0: x_micro ; Q (+bf16 copy) -------------------------
__global__ __launch_bounds__(256) void k_proj_q(
    const float* __restrict__ micro, const float* __restrict__ mp_w,
    const float* __restrict__ mp_b, const float* __restrict__ wq)
{
    const int RB = 32;
    __shared__ float s_micro[RB][DM];
    __shared__ float s_mpw[DM][DMODEL];
    __shared__ float s_x[RB][DMODEL];
    const int t = threadIdx.x;
    const int row0 = blockIdx.x * RB;

    for (int i = t; i < RB * DM; i += 256)
        s_micro[i / DM][i % DM] = micro[(size_t)row0 * DM + i];
    for (int i = t; i < DM * DMODEL; i += 256)
        s_mpw[i / DMODEL][i % DMODEL] = mp_w[i];
    __syncthreads();

    const float bias = mp_b[t];
    for (int r = 0; r < RB; r++) {
        float acc = 0.f;
#pragma unroll
        for (int i = 0; i < DM; i++)
            acc = fmaf(s_micro[r][i], s_mpw[i][t], acc);
        acc = acc + bias;
        s_x[r][t] = acc;
        g_xmicro[(size_t)(row0 + r) * DMODEL + t] = acc;
    }
    __syncthreads();

    float q[RB];
#pragma unroll
    for (int r = 0; r < RB; r++) q[r] = 0.f;
    for (int d = 0; d < DMODEL; d += 2) {
        const float w0 = wq[(size_t)d * DMODEL + t];
        const float w1 = wq[(size_t)(d + 1) * DMODEL + t];
#pragma unroll
        for (int r = 0; r < RB; r++) {
            float2 x2 = *(const float2*)&s_x[r][d];
            q[r] = fmaf(x2.y, w1, fmaf(x2.x, w0, q[r]));
        }
    }
    for (int r = 0; r < RB; r++) {
        const float v = q[r];
        const size_t o = (size_t)(row0 + r) * DMODEL + t;
        g_Q[o] = v;
        g_Qb[o] = __float2bfloat16(v);
    }
}

// ---------------- kernel 1: K_full, V_full (+bf16 copy of K) -----------------
__global__ __launch_bounds__(256) void k_proj_kv(
    const float* __restrict__ macro, const float* __restrict__ wk,
    const float* __restrict__ wv)
{
    const int RB = 32;
    __shared__ float s_x[DMODEL][RB + 2];
    const int t = threadIdx.x;
    const int row0 = blockIdx.x * RB;

#pragma unroll 4
    for (int r = 0; r < RB; r++)
        s_x[t][r] = macro[(size_t)(row0 + r) * DMODEL + t];
    __syncthreads();

    uint64_t ka2[RB / 2], va2[RB / 2];
#pragma unroll
    for (int p = 0; p < RB / 2; p++) { ka2[p] = 0ull; va2[p] = 0ull; }

    for (int d = 0; d < DMODEL; d++) {
        const float kw = wk[(size_t)d * DMODEL + t];
        const float vw = wv[(size_t)d * DMODEL + t];
        const uint64_t kw2 = pack2(kw, kw);
        const uint64_t vw2 = pack2(vw, vw);
#pragma unroll
        for (int p = 0; p < RB / 2; p++) {
            const uint64_t x2 = *(const uint64_t*)&s_x[d][2 * p];
            ka2[p] = ffma2(x2, kw2, ka2[p]);
            va2[p] = ffma2(x2, vw2, va2[p]);
        }
    }
#pragma unroll
    for (int p = 0; p < RB / 2; p++) {
        float k0, k1, v0, v1;
        unpack2(ka2[p], k0, k1);
        unpack2(va2[p], v0, v1);
        const size_t o0 = (size_t)(row0 + 2 * p) * DMODEL + t;
        const size_t o1 = o0 + DMODEL;
        g_Kf[o0] = k0; g_Kf[o1] = k1;
        g_Vf[o0] = v0; g_Vf[o1] = v1;
        g_Kb[o0] = __float2bfloat16(k0);
        g_Kb[o1] = __float2bfloat16(k1);
    }
}

// ---------------- kernel 2: approx-score 16-bit radix keys via bf16 GEMM -----
#define KT 32
#define SSTR 40
__global__ __launch_bounds__(256) void k_mma_scores()
{
    __shared__ __align__(16) __nv_bfloat16 sA[2][128 * SSTR];
    __shared__ __align__(16) __nv_bfloat16 sB[2][128 * SSTR];

    const int t = threadIdx.x;
    const int lane = t & 31, warp = t >> 5;
    const int b = blockIdx.z;
    const int q0 = blockIdx.y * 128;
    const int c0 = blockIdx.x * 128;

    const __nv_bfloat16* A = g_Qb + (size_t)b * ND * DMODEL;
    const __nv_bfloat16* B = g_Kb + (size_t)b * NC * DMODEL;

    const int wq0 = (warp & 1) * 64;
    const int wc0 = (warp >> 1) * 32;

    float acc[4][4][4];
#pragma unroll
    for (int i = 0; i < 4; i++)
#pragma unroll
        for (int j = 0; j < 4; j++)
#pragma unroll
            for (int k = 0; k < 4; k++) acc[i][j][k] = 0.f;

    const uint32_t abase0 = smem_u32(sA[0]), abase1 = smem_u32(sA[1]);
    const uint32_t bbase0 = smem_u32(sB[0]), bbase1 = smem_u32(sB[1]);
    const int lr = t >> 2;
    const int lc8 = (t & 3) * 8;
    const int arow = lane & 15, ak8 = (lane >> 4) * 8;
    const int brow = ((lane >> 3) & 1) * 8 + (lane & 7), bk8 = (lane >> 4) * 8;

    auto load_tile = [&](int st, int kt) {
        const uint32_t ab = st ? abase1 : abase0;
        const uint32_t bb = st ? bbase1 : bbase0;
        const int kb = kt * KT;
#pragma unroll
        for (int i = 0; i < 2; i++) {
            const int r = lr + i * 64;
            const uint32_t soff = (uint32_t)(r * SSTR + lc8) * 2;
            cp16(ab + soff, A + (size_t)(q0 + r) * DMODEL + kb + lc8);
            cp16(bb + soff, B + (size_t)(c0 + r) * DMODEL + kb + lc8);
        }
        cp_commit();
    };

    const int NT = DMODEL / KT;  // 8
    load_tile(0, 0);
    int cur = 0;
    for (int kt = 0; kt < NT; kt++) {
        if (kt + 1 < NT) {
            load_tile(cur ^ 1, kt + 1);
            cp_wait1();
        } else {
            cp_wait0();
        }
        __syncthreads();

        const uint32_t ab = cur ? abase1 : abase0;
        const uint32_t bb = cur ? bbase1 : bbase0;
#pragma unroll
        for (int ks = 0; ks < 2; ks++) {
            const int k0 = ks * 16;
            uint32_t af[4][4], bf[4][2];
#pragma unroll
            for (int mt = 0; mt < 4; mt++) {
                const uint32_t off =
                    (uint32_t)((wq0 + mt * 16 + arow) * SSTR + k0 + ak8) * 2;
                ldsm4(af[mt][0], af[mt][1], af[mt][2], af[mt][3], ab + off);
            }
#pragma unroll
            for (int nh = 0; nh < 2; nh++) {
                const uint32_t off =
                    (uint32_t)((wc0 + nh * 16 + brow) * SSTR + k0 + bk8) * 2;
                uint32_t r0, r1, r2, r3;
                ldsm4(r0, r1, r2, r3, bb + off);
                bf[nh * 2 + 0][0] = r0; bf[nh * 2 + 0][1] = r2;
                bf[nh * 2 + 1][0] = r1; bf[nh * 2 + 1][1] = r3;
            }
#pragma unroll
            for (int mt = 0; mt < 4; mt++)
#pragma unroll
                for (int nt = 0; nt < 4; nt++) {
                    float* d = acc[mt][nt];
                    mma16816(d[0], d[1], d[2], d[3], af[mt][0], af[mt][1],
                             af[mt][2], af[mt][3], bf[nt][0], bf[nt][1]);
                }
        }
        __syncthreads();
        cur ^= 1;
    }

    // epilogue: write packed 16-bit keys (2 per uint32 store)
    const int g = lane >> 2, tg = lane & 3;
    uint16_t* __restrict__ Ck = g_keys16 + (size_t)b * ND * NC;
#pragma unroll
    for (int mt = 0; mt < 4; mt++) {
#pragma unroll
        for (int nt = 0; nt < 4; nt++) {
            const float* d = acc[mt][nt];
            const int qrow = q0 + wq0 + mt * 16 + g;
            const int col = c0 + wc0 + nt * 8 + tg * 2;
            const uint32_t lo = (fkey(d[0]) >> 16) | (fkey(d[1]) & 0xFFFF0000u);
            const uint32_t hi = (fkey(d[2]) >> 16) | (fkey(d[3]) & 0xFFFF0000u);
            *(uint32_t*)(Ck + (size_t)qrow * NC + col) = lo;
            *(uint32_t*)(Ck + (size_t)(qrow + 8) * NC + col) = hi;
        }
    }
}

// ---------------- kernel 3: FUSED select + exact refine + top-32 + softmax ---
__device__ __forceinline__ void hist_add_full(int b, int* hist) {
    unsigned m = __match_any_sync(0xffffffffu, b);
    if ((threadIdx.x & 31) == (__ffs(m) - 1)) atomicAdd(&hist[b], __popc(m));
}

__global__ __launch_bounds__(256) void k_select(float* __restrict__ out_attn,
                                                float* __restrict__ out_idxf)
{
    const int q = blockIdx.x;
    const int b = q / ND;
    const uint16_t* __restrict__ row = g_keys16 + (size_t)q * NC;
    const int t = threadIdx.x;
    const int lane = t & 31, warp = t >> 5;

    __shared__ int s_hist[256];
    __shared__ int s_S[257];
    __shared__ int s_info[2];
    __shared__ int s_candi[NCMAX];
    __shared__ int s_cnt;
    __shared__ float s_q[DMODEL];
    __shared__ float s_v[NCMAX];
    __shared__ int   s_i[NCMAX];
    __shared__ float s_topv[TOPK];
    __shared__ int   s_topi[TOPK];

    if (t < 256) s_hist[t] = 0;
    if (t == 0) { s_S[256] = 0; s_cnt = 0; }
    // Q row into smem (used by refine phase)
    s_q[t] = g_Q[(size_t)q * DMODEL + t];
    __syncthreads();

    // 32 keys per thread, packed 2-per-uint32 in 16 registers
    uint32_t kp[16];
#pragma unroll
    for (int i = 0; i < 4; i++) {
        const uint4 k4 = *(const uint4*)(row + i * 2048 + t * 8);
        kp[i * 4 + 0] = k4.x; kp[i * 4 + 1] = k4.y;
        kp[i * 4 + 2] = k4.z; kp[i * 4 + 3] = k4.w;
    }
    // pass-0 histogram: high byte of each 16-bit key
#pragma unroll
    for (int w = 0; w < 16; w++) {
        hist_add_full((kp[w] >> 8) & 255, s_hist);
        hist_add_full(kp[w] >> 24, s_hist);
    }
    __syncthreads();

    int need = NCAND;
    uint32_t T16 = 0;
    for (int p = 0; p < 2; p++) {
        if (warp == 0) {
            const int base = lane * 8;
            int c[8];
#pragma unroll
            for (int k2 = 0; k2 < 8; k2++) c[k2] = s_hist[base + k2];
            int sum = 0;
#pragma unroll
            for (int k2 = 7; k2 >= 0; k2--) { sum += c[k2]; c[k2] = sum; }
            int v = sum;
#pragma unroll
            for (int off = 1; off < 32; off <<= 1) {
                int o = __shfl_down_sync(0xffffffffu, v, off);
                if (lane + off < 32) v += o;
            }
            const int run = v - sum;
#pragma unroll
            for (int k2 = 0; k2 < 8; k2++) s_S[base + k2] = c[k2] + run;
        }
        __syncthreads();
        if (t < 256) {
            if (s_S[t] >= need && s_S[t + 1] < need) {
                s_info[0] = t;
                s_info[1] = s_S[t + 1];
            }
        }
        __syncthreads();
        const int B = s_info[0];
        need -= s_info[1];
        T16 = (T16 << 8) | (uint32_t)B;

        if (p == 0) {
            if (t < 256) s_hist[t] = 0;
            __syncthreads();
#pragma unroll
            for (int w = 0; w < 16; w++) {
                const uint32_t klo = kp[w] & 0xFFFFu;
                const uint32_t khi = kp[w] >> 16;
                if ((klo >> 8) == (uint32_t)B) atomicAdd(&s_hist[klo & 255], 1);
                if ((khi >> 8) == (uint32_t)B) atomicAdd(&s_hist[khi & 255], 1);
            }
            __syncthreads();
        }
    }

    // collect ALL keys >= T16 (superset of exact top-32 by monotonicity)
#pragma unroll
    for (int w = 0; w < 16; w++) {
        const uint32_t klo = kp[w] & 0xFFFFu;
        const uint32_t khi = kp[w] >> 16;
        const int base = (w >> 2) * 2048 + t * 8 + (w & 3) * 2;
        if (klo >= T16) {
            const int pos = atomicAdd(&s_cnt, 1);
            if (pos < NCMAX) s_candi[pos] = base;
        }
        if (khi >= T16) {
            const int pos = atomicAdd(&s_cnt, 1);
            if (pos < NCMAX) s_candi[pos] = base + 1;
        }
    }
    __syncthreads();

    const int cnt = min(s_cnt, NCMAX);

    // ---- exact refine (reference-bit-exact fp32 chain) ----
    float val = -FLT_MAX;
    int ci = NC + t;  // unique invalid index for pad slots
    if (t < cnt) {
        ci = s_candi[t];
        const float* __restrict__ kr = g_Kf + ((size_t)b * NC + ci) * DMODEL;
        float acc = 0.f;
#pragma unroll 16
        for (int d4 = 0; d4 < DMODEL / 4; d4++) {
            const float4 kv = __ldg((const float4*)(kr + d4 * 4));
            acc = fmaf(s_q[d4 * 4 + 0], kv.x, acc);
            acc = fmaf(s_q[d4 * 4 + 1], kv.y, acc);
            acc = fmaf(s_q[d4 * 4 + 2], kv.z, acc);
            acc = fmaf(s_q[d4 * 4 + 3], kv.w, acc);
        }
        val = acc * 0.0625f;
    }
    if (t < NCMAX) { s_v[t] = val; s_i[t] = ci; }
    __syncthreads();

    // ---- rank-sort the (<=128) candidates by (value desc, index asc) ----
    if (t < NCMAX) {
        int rank = 0;
#pragma unroll 8
        for (int j = 0; j < NCMAX; j++) {
            const float ov = s_v[j];
            const int oi = s_i[j];
            rank += (ov > val) || (ov == val && oi < ci);
        }
        if (rank < TOPK) { s_topv[rank] = val; s_topi[rank] = ci; }
    }
    __syncthreads();

    // ---- softmax + outputs (warp 0) ----
    if (warp == 0) {
        const float v = s_topv[lane];
        float m = v;
#pragma unroll
        for (int s = 16; s > 0; s >>= 1)
            m = fmaxf(m, __shfl_xor_sync(0xffffffffu, m, s));
        const float e = expf(v - m);
        float sum = e;
#pragma unroll
        for (int s = 16; s > 0; s >>= 1)
            sum += __shfl_xor_sync(0xffffffffu, sum, s);
        const float a = e / sum;
        out_attn[(size_t)q * TOPK + lane] = a;
        out_idxf[(size_t)q * TOPK + lane] = (float)s_topi[lane];
        g_attn[(size_t)q * TOPK + lane] = a;
        g_idx[(size_t)q * TOPK + lane] = s_topi[lane];
    }
}

// ---------------- kernel 4: context gather + out proj + residual -------------
__global__ __launch_bounds__(256) void k_final(const float* __restrict__ op_w,
                                               const float* __restrict__ op_b,
                                               float* __restrict__ out)
{
    const int QB = 8;
    __shared__ float s_attn[QB][TOPK];
    __shared__ int s_idx2[QB][TOPK];
    __shared__ float s_ctx[QB][DMODEL];
    const int t = threadIdx.x;
    const int q0 = blockIdx.x * QB;
    const int b = q0 / ND;

    if (t < QB * TOPK) {
        s_attn[t / TOPK][t & 31] = g_attn[(size_t)q0 * TOPK + t];
        s_idx2[t / TOPK][t & 31] = g_idx[(size_t)q0 * TOPK + t];
    }
    __syncthreads();

    const float* __restrict__ V = g_Vf + (size_t)b * NC * DMODEL;
#pragma unroll
    for (int r = 0; r < QB; r++) {
        float c = 0.f;
#pragma unroll 8
        for (int k = 0; k < TOPK; k++)
            c = fmaf(s_attn[r][k], V[(size_t)s_idx2[r][k] * DMODEL + t], c);
        s_ctx[r][t] = c;
    }
    __syncthreads();

    float o[QB];
    const float bias = op_b[t];
#pragma unroll
    for (int r = 0; r < QB; r++) o[r] = 0.f;

    for (int d = 0; d < DMODEL; d += 2) {
        const float w0 = op_w[(size_t)d * DMODEL + t];
        const float w1 = op_w[(size_t)(d + 1) * DMODEL + t];
#pragma unroll
        for (int r = 0; r < QB; r++) {
            float2 c2 = *(const float2*)&s_ctx[r][d];
            o[r] = fmaf(c2.y, w1, fmaf(c2.x, w0, o[r]));
        }
    }
#pragma unroll
    for (int r = 0; r < QB; r++)
        out[(size_t)(q0 + r) * DMODEL + t] =
            g_xmicro[(size_t)(q0 + r) * DMODEL + t] + o[r] + bias;
}

// ---------------- launch -----------------------------------------------------
extern "C" void kernel_launch(void* const* d_in, const int* in_sizes, int n_in,
                              void* d_out, int out_size)
{
    const float* micro = (const float*)d_in[0];
    const float* macro = (const float*)d_in[1];
    const float* mp_w = (const float*)d_in[2];
    const float* mp_b = (const float*)d_in[3];
    const float* wq = (const float*)d_in[4];
    const float* wk = (const float*)d_in[5];
    const float* wv = (const float*)d_in[6];
    const float* op_w = (const float*)d_in[7];
    const float* op_b = (const float*)d_in[8];

    float* out = (float*)d_out;
    float* out_attn = out + (size_t)BSZ * ND * DMODEL;
    float* out_idxf = out_attn + (size_t)BSZ * ND * TOPK;

    k_proj_q<<<(BSZ * ND) / 32, 256>>>(micro, mp_w, mp_b, wq);
    k_proj_kv<<<(BSZ * NC) / 32, 256>>>(macro, wk, wv);
    dim3 gm(NC / 128, ND / 128, BSZ);
    k_mma_scores<<<gm, 256>>>();
    k_select<<<BSZ * ND, 256>>>(out_attn, out_idxf);
    k_final<<<(BSZ * ND) / 8, 256>>>(op_w, op_b, out);
}

// round 13
// speedup vs baseline: 1.5585x; 1.5585x over previous
#include <cuda_runtime.h>
#include <cuda_bf16.h>
#include <float.h>
#include <math.h>
#include <stdint.h>

#define BSZ 4
#define ND 2048
#define NC 8192
#define DM 11
#define DMODEL 256
#define TOPK 32
#define NCAND 64
#define NCMAX 128

// ---------------- scratch (no allocations allowed) ----------------
__device__ float g_xmicro[BSZ * ND * DMODEL];
__device__ float g_Q[BSZ * ND * DMODEL];
__device__ float g_Kf[BSZ * NC * DMODEL];
__device__ float g_Vf[BSZ * NC * DMODEL];
__device__ uint16_t g_keys16[(size_t)BSZ * ND * NC];     // 16-bit radix keys
__device__ __nv_bfloat16 g_Qb[(size_t)BSZ * ND * DMODEL];
__device__ __nv_bfloat16 g_Kb[(size_t)BSZ * NC * DMODEL];
__device__ float g_attn[BSZ * ND * TOPK];
__device__ int   g_idx[BSZ * ND * TOPK];

// ---------------- packed f32x2 helpers ---------------------------------------
__device__ __forceinline__ uint64_t pack2(float lo, float hi) {
    uint64_t d;
    asm("mov.b64 %0, {%1, %2};" : "=l"(d) : "f"(lo), "f"(hi));
    return d;
}
__device__ __forceinline__ void unpack2(uint64_t v, float& lo, float& hi) {
    asm("mov.b64 {%0, %1}, %2;" : "=f"(lo), "=f"(hi) : "l"(v));
}
__device__ __forceinline__ uint64_t ffma2(uint64_t a, uint64_t b, uint64_t c) {
    uint64_t d;
    asm("fma.rn.f32x2 %0, %1, %2, %3;" : "=l"(d) : "l"(a), "l"(b), "l"(c));
    return d;
}

// ---------------- mma.sync / cp.async helpers --------------------------------
__device__ __forceinline__ uint32_t smem_u32(const void* p) {
    uint32_t a;
    asm("{ .reg .u64 t; cvta.to.shared.u64 t, %1; cvt.u32.u64 %0, t; }"
        : "=r"(a) : "l"(p));
    return a;
}
__device__ __forceinline__ void cp16(uint32_t dst, const void* src) {
    asm volatile("cp.async.ca.shared.global [%0], [%1], 16;"
                 :: "r"(dst), "l"(src));
}
__device__ __forceinline__ void cp_commit() {
    asm volatile("cp.async.commit_group;");
}
__device__ __forceinline__ void cp_wait1() {
    asm volatile("cp.async.wait_group 1;");
}
__device__ __forceinline__ void cp_wait0() {
    asm volatile("cp.async.wait_group 0;");
}
__device__ __forceinline__ void ldsm4(uint32_t& r0, uint32_t& r1, uint32_t& r2,
                                      uint32_t& r3, uint32_t addr) {
    asm volatile("ldmatrix.sync.aligned.m8n8.x4.shared.b16 {%0,%1,%2,%3}, [%4];"
                 : "=r"(r0), "=r"(r1), "=r"(r2), "=r"(r3) : "r"(addr));
}
__device__ __forceinline__ void mma16816(float& d0, float& d1, float& d2,
                                         float& d3, uint32_t a0, uint32_t a1,
                                         uint32_t a2, uint32_t a3, uint32_t b0,
                                         uint32_t b1) {
    asm volatile(
        "mma.sync.aligned.m16n8k16.row.col.f32.bf16.bf16.f32 "
        "{%0,%1,%2,%3}, {%4,%5,%6,%7}, {%8,%9}, {%0,%1,%2,%3};"
        : "+f"(d0), "+f"(d1), "+f"(d2), "+f"(d3)
        : "r"(a0), "r"(a1), "r"(a2), "r"(a3), "r"(b0), "r"(b1));
}
__device__ __forceinline__ uint32_t fkey(float v) {
    uint32_t u = __float_as_uint(v);
    return (u & 0x80000000u) ? ~u : (u | 0x80000000u);
}

// ---------------- kernel 0: x_micro ; Q (+bf16 copy) -------------------------
__global__ __launch_bounds__(256) void k_proj_q(
    const float* __restrict__ micro, const float* __restrict__ mp_w,
    const float* __restrict__ mp_b, const float* __restrict__ wq)
{
    const int RB = 32;
    __shared__ float s_micro[RB][DM];
    __shared__ float s_mpw[DM][DMODEL];
    __shared__ float s_x[RB][DMODEL];
    const int t = threadIdx.x;
    const int row0 = blockIdx.x * RB;

    for (int i = t; i < RB * DM; i += 256)
        s_micro[i / DM][i % DM] = micro[(size_t)row0 * DM + i];
    for (int i = t; i < DM * DMODEL; i += 256)
        s_mpw[i / DMODEL][i % DMODEL] = mp_w[i];
    __syncthreads();

    const float bias = mp_b[t];
    for (int r = 0; r < RB; r++) {
        float acc = 0.f;
#pragma unroll
        for (int i = 0; i < DM; i++)
            acc = fmaf(s_micro[r][i], s_mpw[i][t], acc);
        acc = acc + bias;
        s_x[r][t] = acc;
        g_xmicro[(size_t)(row0 + r) * DMODEL + t] = acc;
    }
    __syncthreads();

    float q[RB];
#pragma unroll
    for (int r = 0; r < RB; r++) q[r] = 0.f;
    for (int d = 0; d < DMODEL; d += 2) {
        const float w0 = wq[(size_t)d * DMODEL + t];
        const float w1 = wq[(size_t)(d + 1) * DMODEL + t];
#pragma unroll
        for (int r = 0; r < RB; r++) {
            float2 x2 = *(const float2*)&s_x[r][d];
            q[r] = fmaf(x2.y, w1, fmaf(x2.x, w0, q[r]));
        }
    }
    for (int r = 0; r < RB; r++) {
        const float v = q[r];
        const size_t o = (size_t)(row0 + r) * DMODEL + t;
        g_Q[o] = v;
        g_Qb[o] = __float2bfloat16(v);
    }
}

// ---------------- kernel 1: K_full, V_full (+bf16 copy of K) -----------------
__global__ __launch_bounds__(256) void k_proj_kv(
    const float* __restrict__ macro, const float* __restrict__ wk,
    const float* __restrict__ wv)
{
    const int RB = 32;
    __shared__ float s_x[DMODEL][RB + 2];
    const int t = threadIdx.x;
    const int row0 = blockIdx.x * RB;

#pragma unroll 4
    for (int r = 0; r < RB; r++)
        s_x[t][r] = macro[(size_t)(row0 + r) * DMODEL + t];
    __syncthreads();

    uint64_t ka2[RB / 2], va2[RB / 2];
#pragma unroll
    for (int p = 0; p < RB / 2; p++) { ka2[p] = 0ull; va2[p] = 0ull; }

    for (int d = 0; d < DMODEL; d++) {
        const float kw = wk[(size_t)d * DMODEL + t];
        const float vw = wv[(size_t)d * DMODEL + t];
        const uint64_t kw2 = pack2(kw, kw);
        const uint64_t vw2 = pack2(vw, vw);
#pragma unroll
        for (int p = 0; p < RB / 2; p++) {
            const uint64_t x2 = *(const uint64_t*)&s_x[d][2 * p];
            ka2[p] = ffma2(x2, kw2, ka2[p]);
            va2[p] = ffma2(x2, vw2, va2[p]);
        }
    }
#pragma unroll
    for (int p = 0; p < RB / 2; p++) {
        float k0, k1, v0, v1;
        unpack2(ka2[p], k0, k1);
        unpack2(va2[p], v0, v1);
        const size_t o0 = (size_t)(row0 + 2 * p) * DMODEL + t;
        const size_t o1 = o0 + DMODEL;
        g_Kf[o0] = k0; g_Kf[o1] = k1;
        g_Vf[o0] = v0; g_Vf[o1] = v1;
        g_Kb[o0] = __float2bfloat16(k0);
        g_Kb[o1] = __float2bfloat16(k1);
    }
}

// ---------------- kernel 2: approx-score 16-bit radix keys via bf16 GEMM -----
#define KT 32
#define SSTR 40
__global__ __launch_bounds__(256) void k_mma_scores()
{
    __shared__ __align__(16) __nv_bfloat16 sA[2][128 * SSTR];
    __shared__ __align__(16) __nv_bfloat16 sB[2][128 * SSTR];

    const int t = threadIdx.x;
    const int lane = t & 31, warp = t >> 5;
    const int b = blockIdx.z;
    const int q0 = blockIdx.y * 128;
    const int c0 = blockIdx.x * 128;

    const __nv_bfloat16* A = g_Qb + (size_t)b * ND * DMODEL;
    const __nv_bfloat16* B = g_Kb + (size_t)b * NC * DMODEL;

    const int wq0 = (warp & 1) * 64;
    const int wc0 = (warp >> 1) * 32;

    float acc[4][4][4];
#pragma unroll
    for (int i = 0; i < 4; i++)
#pragma unroll
        for (int j = 0; j < 4; j++)
#pragma unroll
            for (int k = 0; k < 4; k++) acc[i][j][k] = 0.f;

    const uint32_t abase0 = smem_u32(sA[0]), abase1 = smem_u32(sA[1]);
    const uint32_t bbase0 = smem_u32(sB[0]), bbase1 = smem_u32(sB[1]);
    const int lr = t >> 2;
    const int lc8 = (t & 3) * 8;
    const int arow = lane & 15, ak8 = (lane >> 4) * 8;
    const int brow = ((lane >> 3) & 1) * 8 + (lane & 7), bk8 = (lane >> 4) * 8;

    auto load_tile = [&](int st, int kt) {
        const uint32_t ab = st ? abase1 : abase0;
        const uint32_t bb = st ? bbase1 : bbase0;
        const int kb = kt * KT;
#pragma unroll
        for (int i = 0; i < 2; i++) {
            const int r = lr + i * 64;
            const uint32_t soff = (uint32_t)(r * SSTR + lc8) * 2;
            cp16(ab + soff, A + (size_t)(q0 + r) * DMODEL + kb + lc8);
            cp16(bb + soff, B + (size_t)(c0 + r) * DMODEL + kb + lc8);
        }
        cp_commit();
    };

    const int NT = DMODEL / KT;  // 8
    load_tile(0, 0);
    int cur = 0;
    for (int kt = 0; kt < NT; kt++) {
        if (kt + 1 < NT) {
            load_tile(cur ^ 1, kt + 1);
            cp_wait1();
        } else {
            cp_wait0();
        }
        __syncthreads();

        const uint32_t ab = cur ? abase1 : abase0;
        const uint32_t bb = cur ? bbase1 : bbase0;
#pragma unroll
        for (int ks = 0; ks < 2; ks++) {
            const int k0 = ks * 16;
            uint32_t af[4][4], bf[4][2];
#pragma unroll
            for (int mt = 0; mt < 4; mt++) {
                const uint32_t off =
                    (uint32_t)((wq0 + mt * 16 + arow) * SSTR + k0 + ak8) * 2;
                ldsm4(af[mt][0], af[mt][1], af[mt][2], af[mt][3], ab + off);
            }
#pragma unroll
            for (int nh = 0; nh < 2; nh++) {
                const uint32_t off =
                    (uint32_t)((wc0 + nh * 16 + brow) * SSTR + k0 + bk8) * 2;
                uint32_t r0, r1, r2, r3;
                ldsm4(r0, r1, r2, r3, bb + off);
                bf[nh * 2 + 0][0] = r0; bf[nh * 2 + 0][1] = r2;
                bf[nh * 2 + 1][0] = r1; bf[nh * 2 + 1][1] = r3;
            }
#pragma unroll
            for (int mt = 0; mt < 4; mt++)
#pragma unroll
                for (int nt = 0; nt < 4; nt++) {
                    float* d = acc[mt][nt];
                    mma16816(d[0], d[1], d[2], d[3], af[mt][0], af[mt][1],
                             af[mt][2], af[mt][3], bf[nt][0], bf[nt][1]);
                }
        }
        __syncthreads();
        cur ^= 1;
    }

    // epilogue: write packed 16-bit keys (2 per uint32 store)
    const int g = lane >> 2, tg = lane & 3;
    uint16_t* __restrict__ Ck = g_keys16 + (size_t)b * ND * NC;
#pragma unroll
    for (int mt = 0; mt < 4; mt++) {
#pragma unroll
        for (int nt = 0; nt < 4; nt++) {
            const float* d = acc[mt][nt];
            const int qrow = q0 + wq0 + mt * 16 + g;
            const int col = c0 + wc0 + nt * 8 + tg * 2;
            const uint32_t lo = (fkey(d[0]) >> 16) | (fkey(d[1]) & 0xFFFF0000u);
            const uint32_t hi = (fkey(d[2]) >> 16) | (fkey(d[3]) & 0xFFFF0000u);
            *(uint32_t*)(Ck + (size_t)qrow * NC + col) = lo;
            *(uint32_t*)(Ck + (size_t)(qrow + 8) * NC + col) = hi;
        }
    }
}

// ---------------- kernel 3: FUSED select + exact refine + top-32 + softmax ---
__device__ __forceinline__ void hist_add_full(int b, int* hist) {
    unsigned m = __match_any_sync(0xffffffffu, b);
    if ((threadIdx.x & 31) == (__ffs(m) - 1)) atomicAdd(&hist[b], __popc(m));
}

__global__ __launch_bounds__(256) void k_select(float* __restrict__ out_attn,
                                                float* __restrict__ out_idxf)
{
    const int q = blockIdx.x;
    const int b = q / ND;
    const uint16_t* __restrict__ row = g_keys16 + (size_t)q * NC;
    const int t = threadIdx.x;
    const int lane = t & 31, warp = t >> 5;

    __shared__ int s_hist[256];
    __shared__ int s_S[257];
    __shared__ int s_info[2];
    __shared__ int s_candi[NCMAX];
    __shared__ int s_cnt;
    __shared__ float s_q[DMODEL];
    __shared__ float s_v[NCMAX];
    __shared__ int   s_i[NCMAX];
    __shared__ float s_topv[TOPK];
    __shared__ int   s_topi[TOPK];

    if (t < 256) s_hist[t] = 0;
    if (t == 0) { s_S[256] = 0; s_cnt = 0; }
    // Q row into smem (used by refine phase)
    s_q[t] = g_Q[(size_t)q * DMODEL + t];
    __syncthreads();

    // 32 keys per thread, packed 2-per-uint32 in 16 registers
    uint32_t kp[16];
#pragma unroll
    for (int i = 0; i < 4; i++) {
        const uint4 k4 = *(const uint4*)(row + i * 2048 + t * 8);
        kp[i * 4 + 0] = k4.x; kp[i * 4 + 1] = k4.y;
        kp[i * 4 + 2] = k4.z; kp[i * 4 + 3] = k4.w;
    }
    // pass-0 histogram: high byte of each 16-bit key
#pragma unroll
    for (int w = 0; w < 16; w++) {
        hist_add_full((kp[w] >> 8) & 255, s_hist);
        hist_add_full(kp[w] >> 24, s_hist);
    }
    __syncthreads();

    int need = NCAND;
    uint32_t T16 = 0;
    for (int p = 0; p < 2; p++) {
        if (warp == 0) {
            const int base = lane * 8;
            int c[8];
#pragma unroll
            for (int k2 = 0; k2 < 8; k2++) c[k2] = s_hist[base + k2];
            int sum = 0;
#pragma unroll
            for (int k2 = 7; k2 >= 0; k2--) { sum += c[k2]; c[k2] = sum; }
            int v = sum;
#pragma unroll
            for (int off = 1; off < 32; off <<= 1) {
                int o = __shfl_down_sync(0xffffffffu, v, off);
                if (lane + off < 32) v += o;
            }
            const int run = v - sum;
#pragma unroll
            for (int k2 = 0; k2 < 8; k2++) s_S[base + k2] = c[k2] + run;
        }
        __syncthreads();
        if (t < 256) {
            if (s_S[t] >= need && s_S[t + 1] < need) {
                s_info[0] = t;
                s_info[1] = s_S[t + 1];
            }
        }
        __syncthreads();
        const int B = s_info[0];
        need -= s_info[1];
        T16 = (T16 << 8) | (uint32_t)B;

        if (p == 0) {
            if (t < 256) s_hist[t] = 0;
            __syncthreads();
#pragma unroll
            for (int w = 0; w < 16; w++) {
                const uint32_t klo = kp[w] & 0xFFFFu;
                const uint32_t khi = kp[w] >> 16;
                if ((klo >> 8) == (uint32_t)B) atomicAdd(&s_hist[klo & 255], 1);
                if ((khi >> 8) == (uint32_t)B) atomicAdd(&s_hist[khi & 255], 1);
            }
            __syncthreads();
        }
    }

    // collect ALL keys >= T16 (superset of exact top-32 by monotonicity)
#pragma unroll
    for (int w = 0; w < 16; w++) {
        const uint32_t klo = kp[w] & 0xFFFFu;
        const uint32_t khi = kp[w] >> 16;
        const int base = (w >> 2) * 2048 + t * 8 + (w & 3) * 2;
        if (klo >= T16) {
            const int pos = atomicAdd(&s_cnt, 1);
            if (pos < NCMAX) s_candi[pos] = base;
        }
        if (khi >= T16) {
            const int pos = atomicAdd(&s_cnt, 1);
            if (pos < NCMAX) s_candi[pos] = base + 1;
        }
    }
    __syncthreads();

    const int cnt = min(s_cnt, NCMAX);

    // ---- exact refine (reference-bit-exact fp32 chain) ----
    float val = -FLT_MAX;
    int ci = NC + t;  // unique invalid index for pad slots
    if (t < cnt) {
        ci = s_candi[t];
        const float* __restrict__ kr = g_Kf + ((size_t)b * NC + ci) * DMODEL;
        float acc = 0.f;
#pragma unroll 16
        for (int d4 = 0; d4 < DMODEL / 4; d4++) {
            const float4 kv = __ldg((const float4*)(kr + d4 * 4));
            acc = fmaf(s_q[d4 * 4 + 0], kv.x, acc);
            acc = fmaf(s_q[d4 * 4 + 1], kv.y, acc);
            acc = fmaf(s_q[d4 * 4 + 2], kv.z, acc);
            acc = fmaf(s_q[d4 * 4 + 3], kv.w, acc);
        }
        val = acc * 0.0625f;
    }
    if (t < NCMAX) { s_v[t] = val; s_i[t] = ci; }
    __syncthreads();

    // ---- rank-sort the (<=128) candidates by (value desc, index asc) ----
    if (t < NCMAX) {
        int rank = 0;
#pragma unroll 8
        for (int j = 0; j < NCMAX; j++) {
            const float ov = s_v[j];
            const int oi = s_i[j];
            rank += (ov > val) || (ov == val && oi < ci);
        }
        if (rank < TOPK) { s_topv[rank] = val; s_topi[rank] = ci; }
    }
    __syncthreads();

    // ---- softmax + outputs (warp 0) ----
    if (warp == 0) {
        const float v = s_topv[lane];
        float m = v;
#pragma unroll
        for (int s = 16; s > 0; s >>= 1)
            m = fmaxf(m, __shfl_xor_sync(0xffffffffu, m, s));
        const float e = expf(v - m);
        float sum = e;
#pragma unroll
        for (int s = 16; s > 0; s >>= 1)
            sum += __shfl_xor_sync(0xffffffffu, sum, s);
        const float a = e / sum;
        out_attn[(size_t)q * TOPK + lane] = a;
        out_idxf[(size_t)q * TOPK + lane] = (float)s_topi[lane];
        g_attn[(size_t)q * TOPK + lane] = a;
        g_idx[(size_t)q * TOPK + lane] = s_topi[lane];
    }
}

// ---------------- kernel 4: context gather + out proj + residual -------------
__global__ __launch_bounds__(256) void k_final(const float* __restrict__ op_w,
                                               const float* __restrict__ op_b,
                                               float* __restrict__ out)
{
    const int QB = 8;
    __shared__ float s_attn[QB][TOPK];
    __shared__ int s_idx2[QB][TOPK];
    __shared__ float s_ctx[QB][DMODEL];
    const int t = threadIdx.x;
    const int q0 = blockIdx.x * QB;
    const int b = q0 / ND;

    if (t < QB * TOPK) {
        s_attn[t / TOPK][t & 31] = g_attn[(size_t)q0 * TOPK + t];
        s_idx2[t / TOPK][t & 31] = g_idx[(size_t)q0 * TOPK + t];
    }
    __syncthreads();

    const float* __restrict__ V = g_Vf + (size_t)b * NC * DMODEL;
#pragma unroll
    for (int r = 0; r < QB; r++) {
        float c = 0.f;
#pragma unroll 8
        for (int k = 0; k < TOPK; k++)
            c = fmaf(s_attn[r][k], V[(size_t)s_idx2[r][k] * DMODEL + t], c);
        s_ctx[r][t] = c;
    }
    __syncthreads();

    float o[QB];
    const float bias = op_b[t];
#pragma unroll
    for (int r = 0; r < QB; r++) o[r] = 0.f;

    for (int d = 0; d < DMODEL; d += 2) {
        const float w0 = op_w[(size_t)d * DMODEL + t];
        const float w1 = op_w[(size_t)(d + 1) * DMODEL + t];
#pragma unroll
        for (int r = 0; r < QB; r++) {
            float2 c2 = *(const float2*)&s_ctx[r][d];
            o[r] = fmaf(c2.y, w1, fmaf(c2.x, w0, o[r]));
        }
    }
#pragma unroll
    for (int r = 0; r < QB; r++)
        out[(size_t)(q0 + r) * DMODEL + t] =
            g_xmicro[(size_t)(q0 + r) * DMODEL + t] + o[r] + bias;
}

// ---------------- launch -----------------------------------------------------
extern "C" void kernel_launch(void* const* d_in, const int* in_sizes, int n_in,
                              void* d_out, int out_size)
{
    const float* micro = (const float*)d_in[0];
    const float* macro = (const float*)d_in[1];
    const float* mp_w = (const float*)d_in[2];
    const float* mp_b = (const float*)d_in[3];
    const float* wq = (const float*)d_in[4];
    const float* wk = (const float*)d_in[5];
    const float* wv = (const float*)d_in[6];
    const float* op_w = (const float*)d_in[7];
    const float* op_b = (const float*)d_in[8];

    float* out = (float*)d_out;
    float* out_attn = out + (size_t)BSZ * ND * DMODEL;
    float* out_idxf = out_attn + (size_t)BSZ * ND * TOPK;

    k_proj_q<<<(BSZ * ND) / 32, 256>>>(micro, mp_w, mp_b, wq);
    k_proj_kv<<<(BSZ * NC) / 32, 256>>>(macro, wk, wv);
    dim3 gm(NC / 128, ND / 128, BSZ);
    k_mma_scores<<<gm, 256>>>();
    k_select<<<BSZ * ND, 256>>>(out_attn, out_idxf);
    k_final<<<(BSZ * ND) / 8, 256>>>(op_w, op_b, out);
}

// round 14
// speedup vs baseline: 1.7045x; 1.0937x over previous
#include <cuda_runtime.h>
#include <cuda_bf16.h>
#include <float.h>
#include <math.h>
#include <stdint.h>

#define BSZ 4
#define ND 2048
#define NC 8192
#define DM 11
#define DMODEL 256
#define TOPK 32
#define NCAND 48
#define NCMAX 128

// ---------------- scratch (no allocations allowed) ----------------
__device__ float g_xmicro[BSZ * ND * DMODEL];
__device__ float g_Q[BSZ * ND * DMODEL];
__device__ float g_Kf[BSZ * NC * DMODEL];
__device__ float g_Vf[BSZ * NC * DMODEL];
__device__ uint16_t g_keys16[(size_t)BSZ * ND * NC];     // 16-bit radix keys
__device__ __nv_bfloat16 g_Qb[(size_t)BSZ * ND * DMODEL];
__device__ __nv_bfloat16 g_Kb[(size_t)BSZ * NC * DMODEL];
__device__ float g_attn[BSZ * ND * TOPK];
__device__ int   g_idx[BSZ * ND * TOPK];

// ---------------- packed f32x2 helpers ---------------------------------------
__device__ __forceinline__ uint64_t pack2(float lo, float hi) {
    uint64_t d;
    asm("mov.b64 %0, {%1, %2};" : "=l"(d) : "f"(lo), "f"(hi));
    return d;
}
__device__ __forceinline__ void unpack2(uint64_t v, float& lo, float& hi) {
    asm("mov.b64 {%0, %1}, %2;" : "=f"(lo), "=f"(hi) : "l"(v));
}
__device__ __forceinline__ uint64_t ffma2(uint64_t a, uint64_t b, uint64_t c) {
    uint64_t d;
    asm("fma.rn.f32x2 %0, %1, %2, %3;" : "=l"(d) : "l"(a), "l"(b), "l"(c));
    return d;
}

// ---------------- mma.sync / cp.async helpers --------------------------------
__device__ __forceinline__ uint32_t smem_u32(const void* p) {
    uint32_t a;
    asm("{ .reg .u64 t; cvta.to.shared.u64 t, %1; cvt.u32.u64 %0, t; }"
        : "=r"(a) : "l"(p));
    return a;
}
__device__ __forceinline__ void cp16(uint32_t dst, const void* src) {
    asm volatile("cp.async.ca.shared.global [%0], [%1], 16;"
                 :: "r"(dst), "l"(src));
}
__device__ __forceinline__ void cp_commit() {
    asm volatile("cp.async.commit_group;");
}
__device__ __forceinline__ void cp_wait1() {
    asm volatile("cp.async.wait_group 1;");
}
__device__ __forceinline__ void cp_wait0() {
    asm volatile("cp.async.wait_group 0;");
}
__device__ __forceinline__ void ldsm4(uint32_t& r0, uint32_t& r1, uint32_t& r2,
                                      uint32_t& r3, uint32_t addr) {
    asm volatile("ldmatrix.sync.aligned.m8n8.x4.shared.b16 {%0,%1,%2,%3}, [%4];"
                 : "=r"(r0), "=r"(r1), "=r"(r2), "=r"(r3) : "r"(addr));
}
__device__ __forceinline__ void mma16816(float& d0, float& d1, float& d2,
                                         float& d3, uint32_t a0, uint32_t a1,
                                         uint32_t a2, uint32_t a3, uint32_t b0,
                                         uint32_t b1) {
    asm volatile(
        "mma.sync.aligned.m16n8k16.row.col.f32.bf16.bf16.f32 "
        "{%0,%1,%2,%3}, {%4,%5,%6,%7}, {%8,%9}, {%0,%1,%2,%3};"
        : "+f"(d0), "+f"(d1), "+f"(d2), "+f"(d3)
        : "r"(a0), "r"(a1), "r"(a2), "r"(a3), "r"(b0), "r"(b1));
}
__device__ __forceinline__ uint32_t fkey(float v) {
    uint32_t u = __float_as_uint(v);
    return (u & 0x80000000u) ? ~u : (u | 0x80000000u);
}

// ---------------- kernel 0: FUSED projections (grid-partitioned) -------------
// blocks [0, 1024): K_full/V_full (+bf16 K copy)  — longer path first
// blocks [1024, 1280): x_micro ; Q (+bf16 Q copy)
// Both paths keep their exact fp32 ascending-k chains (bit-identical outputs).
#define KV_BLOCKS ((BSZ * NC) / 32)
#define Q_BLOCKS ((BSZ * ND) / 32)
__global__ __launch_bounds__(256) void k_proj(
    const float* __restrict__ micro, const float* __restrict__ mp_w,
    const float* __restrict__ mp_b, const float* __restrict__ wq,
    const float* __restrict__ macro, const float* __restrict__ wk,
    const float* __restrict__ wv)
{
    __shared__ float pool[11360];  // max(kv: 256*34, q: 352+2816+8192)
    const int t = threadIdx.x;
    const int RB = 32;

    if (blockIdx.x < KV_BLOCKS) {
        // ---------------- KV path ----------------
        float (*s_x)[RB + 2] = (float (*)[RB + 2])pool;  // [DMODEL][34]
        const int row0 = blockIdx.x * RB;

#pragma unroll 4
        for (int r = 0; r < RB; r++)
            s_x[t][r] = macro[(size_t)(row0 + r) * DMODEL + t];
        __syncthreads();

        uint64_t ka2[RB / 2], va2[RB / 2];
#pragma unroll
        for (int p = 0; p < RB / 2; p++) { ka2[p] = 0ull; va2[p] = 0ull; }

        for (int d = 0; d < DMODEL; d++) {
            const float kw = wk[(size_t)d * DMODEL + t];
            const float vw = wv[(size_t)d * DMODEL + t];
            const uint64_t kw2 = pack2(kw, kw);
            const uint64_t vw2 = pack2(vw, vw);
#pragma unroll
            for (int p = 0; p < RB / 2; p++) {
                const uint64_t x2 = *(const uint64_t*)&s_x[d][2 * p];
                ka2[p] = ffma2(x2, kw2, ka2[p]);
                va2[p] = ffma2(x2, vw2, va2[p]);
            }
        }
#pragma unroll
        for (int p = 0; p < RB / 2; p++) {
            float k0, k1, v0, v1;
            unpack2(ka2[p], k0, k1);
            unpack2(va2[p], v0, v1);
            const size_t o0 = (size_t)(row0 + 2 * p) * DMODEL + t;
            const size_t o1 = o0 + DMODEL;
            g_Kf[o0] = k0; g_Kf[o1] = k1;
            g_Vf[o0] = v0; g_Vf[o1] = v1;
            g_Kb[o0] = __float2bfloat16(k0);
            g_Kb[o1] = __float2bfloat16(k1);
        }
    } else {
        // ---------------- Q path ----------------
        float (*s_micro)[DM] = (float (*)[DM])pool;                   // [32][11]
        float (*s_mpw)[DMODEL] = (float (*)[DMODEL])(pool + 352);     // [11][256]
        float (*s_xq)[DMODEL] = (float (*)[DMODEL])(pool + 3168);     // [32][256]
        const int row0 = (blockIdx.x - KV_BLOCKS) * RB;

        for (int i = t; i < RB * DM; i += 256)
            s_micro[i / DM][i % DM] = micro[(size_t)row0 * DM + i];
        for (int i = t; i < DM * DMODEL; i += 256)
            s_mpw[i / DMODEL][i % DMODEL] = mp_w[i];
        __syncthreads();

        const float bias = mp_b[t];
        for (int r = 0; r < RB; r++) {
            float acc = 0.f;
#pragma unroll
            for (int i = 0; i < DM; i++)
                acc = fmaf(s_micro[r][i], s_mpw[i][t], acc);
            acc = acc + bias;  // bias AFTER the sum (XLA fusion order)
            s_xq[r][t] = acc;
            g_xmicro[(size_t)(row0 + r) * DMODEL + t] = acc;
        }
        __syncthreads();

        float q[RB];
#pragma unroll
        for (int r = 0; r < RB; r++) q[r] = 0.f;
        for (int d = 0; d < DMODEL; d += 2) {
            const float w0 = wq[(size_t)d * DMODEL + t];
            const float w1 = wq[(size_t)(d + 1) * DMODEL + t];
#pragma unroll
            for (int r = 0; r < RB; r++) {
                float2 x2 = *(const float2*)&s_xq[r][d];
                q[r] = fmaf(x2.y, w1, fmaf(x2.x, w0, q[r]));
            }
        }
        for (int r = 0; r < RB; r++) {
            const float v = q[r];
            const size_t o = (size_t)(row0 + r) * DMODEL + t;
            g_Q[o] = v;
            g_Qb[o] = __float2bfloat16(v);
        }
    }
}

// ---------------- kernel 1: approx-score 16-bit radix keys via bf16 GEMM -----
#define KT 32
#define SSTR 40
__global__ __launch_bounds__(256) void k_mma_scores()
{
    __shared__ __align__(16) __nv_bfloat16 sA[2][128 * SSTR];
    __shared__ __align__(16) __nv_bfloat16 sB[2][128 * SSTR];

    const int t = threadIdx.x;
    const int lane = t & 31, warp = t >> 5;
    const int b = blockIdx.z;
    const int q0 = blockIdx.y * 128;
    const int c0 = blockIdx.x * 128;

    const __nv_bfloat16* A = g_Qb + (size_t)b * ND * DMODEL;
    const __nv_bfloat16* B = g_Kb + (size_t)b * NC * DMODEL;

    const int wq0 = (warp & 1) * 64;
    const int wc0 = (warp >> 1) * 32;

    float acc[4][4][4];
#pragma unroll
    for (int i = 0; i < 4; i++)
#pragma unroll
        for (int j = 0; j < 4; j++)
#pragma unroll
            for (int k = 0; k < 4; k++) acc[i][j][k] = 0.f;

    const uint32_t abase0 = smem_u32(sA[0]), abase1 = smem_u32(sA[1]);
    const uint32_t bbase0 = smem_u32(sB[0]), bbase1 = smem_u32(sB[1]);
    const int lr = t >> 2;
    const int lc8 = (t & 3) * 8;
    const int arow = lane & 15, ak8 = (lane >> 4) * 8;
    const int brow = ((lane >> 3) & 1) * 8 + (lane & 7), bk8 = (lane >> 4) * 8;

    auto load_tile = [&](int st, int kt) {
        const uint32_t ab = st ? abase1 : abase0;
        const uint32_t bb = st ? bbase1 : bbase0;
        const int kb = kt * KT;
#pragma unroll
        for (int i = 0; i < 2; i++) {
            const int r = lr + i * 64;
            const uint32_t soff = (uint32_t)(r * SSTR + lc8) * 2;
            cp16(ab + soff, A + (size_t)(q0 + r) * DMODEL + kb + lc8);
            cp16(bb + soff, B + (size_t)(c0 + r) * DMODEL + kb + lc8);
        }
        cp_commit();
    };

    const int NT = DMODEL / KT;  // 8
    load_tile(0, 0);
    int cur = 0;
    for (int kt = 0; kt < NT; kt++) {
        if (kt + 1 < NT) {
            load_tile(cur ^ 1, kt + 1);
            cp_wait1();
        } else {
            cp_wait0();
        }
        __syncthreads();

        const uint32_t ab = cur ? abase1 : abase0;
        const uint32_t bb = cur ? bbase1 : bbase0;
#pragma unroll
        for (int ks = 0; ks < 2; ks++) {
            const int k0 = ks * 16;
            uint32_t af[4][4], bf[4][2];
#pragma unroll
            for (int mt = 0; mt < 4; mt++) {
                const uint32_t off =
                    (uint32_t)((wq0 + mt * 16 + arow) * SSTR + k0 + ak8) * 2;
                ldsm4(af[mt][0], af[mt][1], af[mt][2], af[mt][3], ab + off);
            }
#pragma unroll
            for (int nh = 0; nh < 2; nh++) {
                const uint32_t off =
                    (uint32_t)((wc0 + nh * 16 + brow) * SSTR + k0 + bk8) * 2;
                uint32_t r0, r1, r2, r3;
                ldsm4(r0, r1, r2, r3, bb + off);
                bf[nh * 2 + 0][0] = r0; bf[nh * 2 + 0][1] = r2;
                bf[nh * 2 + 1][0] = r1; bf[nh * 2 + 1][1] = r3;
            }
#pragma unroll
            for (int mt = 0; mt < 4; mt++)
#pragma unroll
                for (int nt = 0; nt < 4; nt++) {
                    float* d = acc[mt][nt];
                    mma16816(d[0], d[1], d[2], d[3], af[mt][0], af[mt][1],
                             af[mt][2], af[mt][3], bf[nt][0], bf[nt][1]);
                }
        }
        __syncthreads();
        cur ^= 1;
    }

    // epilogue: write packed 16-bit keys (2 per uint32 store)
    const int g = lane >> 2, tg = lane & 3;
    uint16_t* __restrict__ Ck = g_keys16 + (size_t)b * ND * NC;
#pragma unroll
    for (int mt = 0; mt < 4; mt++) {
#pragma unroll
        for (int nt = 0; nt < 4; nt++) {
            const float* d = acc[mt][nt];
            const int qrow = q0 + wq0 + mt * 16 + g;
            const int col = c0 + wc0 + nt * 8 + tg * 2;
            const uint32_t lo = (fkey(d[0]) >> 16) | (fkey(d[1]) & 0xFFFF0000u);
            const uint32_t hi = (fkey(d[2]) >> 16) | (fkey(d[3]) & 0xFFFF0000u);
            *(uint32_t*)(Ck + (size_t)qrow * NC + col) = lo;
            *(uint32_t*)(Ck + (size_t)(qrow + 8) * NC + col) = hi;
        }
    }
}

// ---------------- kernel 2: FUSED select + exact refine + top-32 + softmax ---
__device__ __forceinline__ void hist_add_full(int b, int* hist) {
    unsigned m = __match_any_sync(0xffffffffu, b);
    if ((threadIdx.x & 31) == (__ffs(m) - 1)) atomicAdd(&hist[b], __popc(m));
}

__global__ __launch_bounds__(256) void k_select(float* __restrict__ out_attn,
                                                float* __restrict__ out_idxf)
{
    const int q = blockIdx.x;
    const int b = q / ND;
    const uint16_t* __restrict__ row = g_keys16 + (size_t)q * NC;
    const int t = threadIdx.x;
    const int lane = t & 31, warp = t >> 5;

    __shared__ int s_hist[256];
    __shared__ int s_S[257];
    __shared__ int s_info[2];
    __shared__ int s_candi[NCMAX];
    __shared__ int s_cnt;
    __shared__ float s_q[DMODEL];
    __shared__ float s_v[NCMAX];
    __shared__ int   s_i[NCMAX];
    __shared__ float s_topv[TOPK];
    __shared__ int   s_topi[TOPK];

    if (t < 256) s_hist[t] = 0;
    if (t == 0) { s_S[256] = 0; s_cnt = 0; }
    s_q[t] = g_Q[(size_t)q * DMODEL + t];
    __syncthreads();

    // 32 keys per thread, packed 2-per-uint32 in 16 registers
    uint32_t kp[16];
#pragma unroll
    for (int i = 0; i < 4; i++) {
        const uint4 k4 = *(const uint4*)(row + i * 2048 + t * 8);
        kp[i * 4 + 0] = k4.x; kp[i * 4 + 1] = k4.y;
        kp[i * 4 + 2] = k4.z; kp[i * 4 + 3] = k4.w;
    }
    // pass-0 histogram: high byte of each 16-bit key
#pragma unroll
    for (int w = 0; w < 16; w++) {
        hist_add_full((kp[w] >> 8) & 255, s_hist);
        hist_add_full(kp[w] >> 24, s_hist);
    }
    __syncthreads();

    int need = NCAND;
    uint32_t T16 = 0;
    for (int p = 0; p < 2; p++) {
        if (warp == 0) {
            const int base = lane * 8;
            int c[8];
#pragma unroll
            for (int k2 = 0; k2 < 8; k2++) c[k2] = s_hist[base + k2];
            int sum = 0;
#pragma unroll
            for (int k2 = 7; k2 >= 0; k2--) { sum += c[k2]; c[k2] = sum; }
            int v = sum;
#pragma unroll
            for (int off = 1; off < 32; off <<= 1) {
                int o = __shfl_down_sync(0xffffffffu, v, off);
                if (lane + off < 32) v += o;
            }
            const int run = v - sum;
#pragma unroll
            for (int k2 = 0; k2 < 8; k2++) s_S[base + k2] = c[k2] + run;
        }
        __syncthreads();
        if (t < 256) {
            if (s_S[t] >= need && s_S[t + 1] < need) {
                s_info[0] = t;
                s_info[1] = s_S[t + 1];
            }
        }
        __syncthreads();
        const int B = s_info[0];
        need -= s_info[1];
        T16 = (T16 << 8) | (uint32_t)B;

        if (p == 0) {
            if (t < 256) s_hist[t] = 0;
            __syncthreads();
#pragma unroll
            for (int w = 0; w < 16; w++) {
                const uint32_t klo = kp[w] & 0xFFFFu;
                const uint32_t khi = kp[w] >> 16;
                if ((klo >> 8) == (uint32_t)B) atomicAdd(&s_hist[klo & 255], 1);
                if ((khi >> 8) == (uint32_t)B) atomicAdd(&s_hist[khi & 255], 1);
            }
            __syncthreads();
        }
    }

    // collect ALL keys >= T16 (superset of exact top-32 by monotonicity)
#pragma unroll
    for (int w = 0; w < 16; w++) {
        const uint32_t klo = kp[w] & 0xFFFFu;
        const uint32_t khi = kp[w] >> 16;
        const int base = (w >> 2) * 2048 + t * 8 + (w & 3) * 2;
        if (klo >= T16) {
            const int pos = atomicAdd(&s_cnt, 1);
            if (pos < NCMAX) s_candi[pos] = base;
        }
        if (khi >= T16) {
            const int pos = atomicAdd(&s_cnt, 1);
            if (pos < NCMAX) s_candi[pos] = base + 1;
        }
    }
    __syncthreads();

    const int cnt = min(s_cnt, NCMAX);

    // ---- exact refine (reference-bit-exact fp32 chain) ----
    float val = -FLT_MAX;
    int ci = NC + t;  // unique invalid index for pad slots
    if (t < cnt) {
        ci = s_candi[t];
        const float* __restrict__ kr = g_Kf + ((size_t)b * NC + ci) * DMODEL;
        float acc = 0.f;
#pragma unroll 16
        for (int d4 = 0; d4 < DMODEL / 4; d4++) {
            const float4 kv = __ldg((const float4*)(kr + d4 * 4));
            acc = fmaf(s_q[d4 * 4 + 0], kv.x, acc);
            acc = fmaf(s_q[d4 * 4 + 1], kv.y, acc);
            acc = fmaf(s_q[d4 * 4 + 2], kv.z, acc);
            acc = fmaf(s_q[d4 * 4 + 3], kv.w, acc);
        }
        val = acc * 0.0625f;
    }
    if (t < NCMAX) { s_v[t] = val; s_i[t] = ci; }
    __syncthreads();

    // ---- rank-sort the cnt candidates by (value desc, index asc) ----
    if (t < cnt) {
        int rank = 0;
#pragma unroll 4
        for (int j = 0; j < cnt; j++) {
            const float ov = s_v[j];
            const int oi = s_i[j];
            rank += (ov > val) || (ov == val && oi < ci);
        }
        if (rank < TOPK) { s_topv[rank] = val; s_topi[rank] = ci; }
    }
    __syncthreads();

    // ---- softmax + outputs (warp 0) ----
    if (warp == 0) {
        const float v = s_topv[lane];
        float m = v;
#pragma unroll
        for (int s = 16; s > 0; s >>= 1)
            m = fmaxf(m, __shfl_xor_sync(0xffffffffu, m, s));
        const float e = expf(v - m);
        float sum = e;
#pragma unroll
        for (int s = 16; s > 0; s >>= 1)
            sum += __shfl_xor_sync(0xffffffffu, sum, s);
        const float a = e / sum;
        out_attn[(size_t)q * TOPK + lane] = a;
        out_idxf[(size_t)q * TOPK + lane] = (float)s_topi[lane];
        g_attn[(size_t)q * TOPK + lane] = a;
        g_idx[(size_t)q * TOPK + lane] = s_topi[lane];
    }
}

// ---------------- kernel 3: context gather + out proj + residual -------------
__global__ __launch_bounds__(256) void k_final(const float* __restrict__ op_w,
                                               const float* __restrict__ op_b,
                                               float* __restrict__ out)
{
    const int QB = 8;
    __shared__ float s_attn[QB][TOPK];
    __shared__ int s_idx2[QB][TOPK];
    __shared__ float s_ctx[QB][DMODEL];
    const int t = threadIdx.x;
    const int q0 = blockIdx.x * QB;
    const int b = q0 / ND;

    if (t < QB * TOPK) {
        s_attn[t / TOPK][t & 31] = g_attn[(size_t)q0 * TOPK + t];
        s_idx2[t / TOPK][t & 31] = g_idx[(size_t)q0 * TOPK + t];
    }
    __syncthreads();

    const float* __restrict__ V = g_Vf + (size_t)b * NC * DMODEL;
#pragma unroll
    for (int r = 0; r < QB; r++) {
        float c = 0.f;
#pragma unroll 8
        for (int k = 0; k < TOPK; k++)
            c = fmaf(s_attn[r][k], V[(size_t)s_idx2[r][k] * DMODEL + t], c);
        s_ctx[r][t] = c;
    }
    __syncthreads();

    float o[QB];
    const float bias = op_b[t];
#pragma unroll
    for (int r = 0; r < QB; r++) o[r] = 0.f;

    for (int d = 0; d < DMODEL; d += 2) {
        const float w0 = op_w[(size_t)d * DMODEL + t];
        const float w1 = op_w[(size_t)(d + 1) * DMODEL + t];
#pragma unroll
        for (int r = 0; r < QB; r++) {
            float2 c2 = *(const float2*)&s_ctx[r][d];
            o[r] = fmaf(c2.y, w1, fmaf(c2.x, w0, o[r]));
        }
    }
#pragma unroll
    for (int r = 0; r < QB; r++)
        out[(size_t)(q0 + r) * DMODEL + t] =
            g_xmicro[(size_t)(q0 + r) * DMODEL + t] + o[r] + bias;
}

// ---------------- launch -----------------------------------------------------
extern "C" void kernel_launch(void* const* d_in, const int* in_sizes, int n_in,
                              void* d_out, int out_size)
{
    const float* micro = (const float*)d_in[0];
    const float* macro = (const float*)d_in[1];
    const float* mp_w = (const float*)d_in[2];
    const float* mp_b = (const float*)d_in[3];
    const float* wq = (const float*)d_in[4];
    const float* wk = (const float*)d_in[5];
    const float* wv = (const float*)d_in[6];
    const float* op_w = (const float*)d_in[7];
    const float* op_b = (const float*)d_in[8];

    float* out = (float*)d_out;
    float* out_attn = out + (size_t)BSZ * ND * DMODEL;
    float* out_idxf = out_attn + (size_t)BSZ * ND * TOPK;

    k_proj<<<KV_BLOCKS + Q_BLOCKS, 256>>>(micro, mp_w, mp_b, wq,
                                          macro, wk, wv);
    dim3 gm(NC / 128, ND / 128, BSZ);
    k_mma_scores<<<gm, 256>>>();
    k_select<<<BSZ * ND, 256>>>(out_attn, out_idxf);
    k_final<<<(BSZ * ND) / 8, 256>>>(op_w, op_b, out);
}